// round 5
// baseline (speedup 1.0000x reference)
#include <cuda_runtime.h>

// involution: B=4, C=256, G=16, K=7, S=1, P=3, R=4, H=W=56
#define BB   4
#define CC   256
#define GG   16
#define CPG  16      // C/G
#define KF   7
#define PAD  3
#define HH   56
#define WW   56
#define CR   64      // C/R
#define KK   49      // K*K
#define KKG  784     // K*K*G
#define TW   28      // pixel tile width (half a row)
#define TQ   (TW/4)
#define NTHREADS 256

#define XSC   128             // channels per xs half
#define XWC   16              // channels per P4 chunk
#define XWW   36              // padded window width
#define KS_FLOATS  (KKG * TW)                 // 21952
#define XS_FLOATS  (XSC * TW)                 // 3584
#define HS_FLOATS  (CR * TW)                  // 1792 (k-major [64][28])
#define REG_FLOATS (XS_FLOATS + HS_FLOATS + 336) // 5712 (>= XWC*KF*XWW = 4032)
#define SMEM_FLOATS (KS_FLOATS + REG_FLOATS)  // 27664 floats = 110656 B

typedef unsigned long long ull;

__device__ __forceinline__ ull fma2(ull a, ull b, ull c) {
    ull d;
    asm("fma.rn.f32x2 %0, %1, %2, %3;" : "=l"(d) : "l"(a), "l"(b), "l"(c));
    return d;
}
__device__ __forceinline__ ull pack2(float v) {
    ull d;
    asm("mov.b64 %0, {%1, %1};" : "=l"(d) : "f"(v));
    return d;
}

__global__ __launch_bounds__(NTHREADS, 2)
void inv_fused_kernel(const float* __restrict__ x,
                      const float* __restrict__ rw,   // [CR][C]
                      const float* __restrict__ rb,   // [CR]
                      const float* __restrict__ sw,   // [KKG][CR]
                      const float* __restrict__ sb,   // [KKG]
                      float* __restrict__ out)
{
    extern __shared__ float smem[];
    float* ks = smem;                    // [KKG][TW] 87.8 KB (rw parked here pre-P3)
    float* xs = smem + KS_FLOATS;        // [XSC][TW]
    float* hs = xs + XS_FLOATS;          // [CR][TW]  k-major (f32x2/float4 aligned)
    float* xw = smem + KS_FLOATS;        // [XWC][KF][XWW] (P4 only, overlays xs/hs)
    float4* xs4  = (float4*)xs;
    float4* rws4 = (float4*)ks;          // staged rw, float4 view

    const int x0   = blockIdx.x * TW;
    const int y    = blockIdx.y;
    const int b    = blockIdx.z;
    const int tid  = threadIdx.x;
    const int warp = tid >> 5;           // 0..7
    const int lane = tid & 31;

    // ---------------- Phase 0: stage rw[64][256] into smem (ks area) -------
    {
        const float4* rwg4 = (const float4*)rw;
        #pragma unroll
        for (int i = tid; i < (CR * CC) / 4; i += NTHREADS)
            rws4[i] = rwg4[i];
    }

    // ---------------- Phase 1+2: hs[o][px] = sum_c rw[o][c]*x[c][px] -------
    // warp w -> o rows 8w..8w+7; lane = px; xs streamed in two 128-ch halves.
    {
        float acc[8];
        #pragma unroll
        for (int j = 0; j < 8; j++) acc[j] = 0.f;
        const int o0 = warp * 8;

        #pragma unroll
        for (int half = 0; half < 2; half++) {
            if (half) __syncthreads();   // WAR on xs
            {
                const float4* xg4 = (const float4*)
                    (x + ((size_t)(b * CC + half * XSC) * HH + y) * WW + x0);
                const int cstride4 = (HH * WW) / 4;
                #pragma unroll
                for (int idx = tid; idx < XSC * TQ; idx += NTHREADS) {
                    int c = idx / TQ;
                    int q = idx - c * TQ;
                    xs4[c * TQ + q] = xg4[(size_t)c * cstride4 + q];
                }
            }
            __syncthreads();

            if (lane < TW) {
                #pragma unroll 2
                for (int kq = 0; kq < XSC / 4; kq++) {
                    float v0 = xs[(4 * kq + 0) * TW + lane];
                    float v1 = xs[(4 * kq + 1) * TW + lane];
                    float v2 = xs[(4 * kq + 2) * TW + lane];
                    float v3 = xs[(4 * kq + 3) * TW + lane];
                    #pragma unroll
                    for (int j = 0; j < 8; j++) {
                        float4 w = rws4[(o0 + j) * (CC / 4) + half * (XSC / 4) + kq];
                        acc[j] += w.x * v0 + w.y * v1 + w.z * v2 + w.w * v3;
                    }
                }
            }
        }
        if (lane < TW) {
            #pragma unroll
            for (int j = 0; j < 8; j++)
                hs[(o0 + j) * TW + lane] = acc[j] + rb[o0 + j];
        }
    }
    __syncthreads();   // hs ready; all rw-in-ks reads done (P3 overwrites ks)

    // ---------------- Phase 3 (f32x2): ks[o][px] = sum_k sw[o][k]*hs[k][px]
    // task = o-pair x full 28-px row (14 packed px). 392 tasks.
    // hs rows are warp-uniform -> v loads are pure LDS broadcasts (1 wf each).
    #pragma unroll 1
    for (int t = tid; t < KKG / 2; t += NTHREADS) {
        const int o0 = t * 2;
        ull acc0[14], acc1[14];
        {
            ull b0 = pack2(sb[o0]);
            ull b1 = pack2(sb[o0 + 1]);
            #pragma unroll
            for (int i = 0; i < 14; i++) { acc0[i] = b0; acc1[i] = b1; }
        }
        const float4* sw4 = (const float4*)(sw + o0 * CR);
        #pragma unroll 2
        for (int kq = 0; kq < CR / 4; kq++) {
            float4 w0q = sw4[kq];
            float4 w1q = sw4[(CR / 4) + kq];
            float wa[4] = {w0q.x, w0q.y, w0q.z, w0q.w};
            float wb[4] = {w1q.x, w1q.y, w1q.z, w1q.w};
            #pragma unroll
            for (int kk = 0; kk < 4; kk++) {
                const int k = kq * 4 + kk;
                ull w20 = pack2(wa[kk]);
                ull w21 = pack2(wb[kk]);
                const ulonglong2* vrow = (const ulonglong2*)(hs + k * TW);
                #pragma unroll
                for (int i = 0; i < 7; i++) {
                    ulonglong2 v = vrow[i];                 // broadcast LDS.128
                    acc0[2 * i + 0] = fma2(w20, v.x, acc0[2 * i + 0]);
                    acc0[2 * i + 1] = fma2(w20, v.y, acc0[2 * i + 1]);
                    acc1[2 * i + 0] = fma2(w21, v.x, acc1[2 * i + 0]);
                    acc1[2 * i + 1] = fma2(w21, v.y, acc1[2 * i + 1]);
                }
            }
        }
        ull* k0 = (ull*)(ks + (size_t)o0 * TW);
        ull* k1 = (ull*)(ks + (size_t)(o0 + 1) * TW);
        #pragma unroll
        for (int i = 0; i < 14; i++) { k0[i] = acc0[i]; k1[i] = acc1[i]; }
    }
    __syncthreads();   // ks complete; xs/hs dead before xw fill

    // ---------------- Phase 4: involution apply ----------------------------
    // subround s: warp w owns group g=8s+w, kern in 49 regs.
    #pragma unroll
    for (int s = 0; s < 2; s++) {
        const int g = 8 * s + warp;
        float kr[KK];
        if (lane < TW) {
            const float* kb = ks + g * KK * TW + lane;
            #pragma unroll
            for (int t = 0; t < KK; t++) kr[t] = kb[t * TW];
        }

        #pragma unroll 1
        for (int j = 0; j < 8; j++) {
            __syncthreads();   // WAR on xw
            {
                float4* xw4 = (float4*)xw;
                const float4 zero4 = make_float4(0.f, 0.f, 0.f, 0.f);
                #pragma unroll
                for (int idx = tid; idx < XWC * KF * (XWW / 4); idx += NTHREADS) {
                    int slot = idx / (KF * (XWW / 4));
                    int rq   = idx - slot * (KF * (XWW / 4));
                    int r    = rq / (XWW / 4);
                    int q    = rq - r * (XWW / 4);
                    int wl   = slot >> 1;
                    int ci   = slot & 1;
                    int c    = (8 * s + wl) * CPG + 2 * j + ci;
                    int yy   = y + r - PAD;
                    int col0 = x0 - 4 + q * 4;
                    float4 v = zero4;
                    if ((unsigned)yy < HH && (unsigned)col0 < WW)
                        v = *(const float4*)(x + ((size_t)(b * CC + c) * HH + yy) * WW + col0);
                    xw4[idx] = v;
                }
            }
            __syncthreads();

            if (lane < TW) {
                #pragma unroll
                for (int ci = 0; ci < 2; ci++) {
                    const float* wrow = xw + ((2 * warp + ci) * KF) * XWW + lane + 1;
                    float a0 = 0.f, a1 = 0.f;
                    #pragma unroll
                    for (int r = 0; r < KF; r++) {
                        #pragma unroll
                        for (int kw = 0; kw < KF; kw++) {
                            float v = wrow[r * XWW + kw];
                            if (kw & 1) a1 += kr[r * KF + kw] * v;
                            else        a0 += kr[r * KF + kw] * v;
                        }
                    }
                    const int c = g * CPG + 2 * j + ci;
                    out[((size_t)(b * CC + c) * HH + y) * WW + x0 + lane] = a0 + a1;
                }
            }
        }
        if (s == 0) __syncthreads();  // xw reads done before next subround
    }
}

extern "C" void kernel_launch(void* const* d_in, const int* in_sizes, int n_in,
                              void* d_out, int out_size)
{
    const float* x  = (const float*)d_in[0];  // (4,256,56,56)
    const float* rw = (const float*)d_in[1];  // (64,256)
    const float* rb = (const float*)d_in[2];  // (64,)
    const float* sw = (const float*)d_in[3];  // (784,64)
    const float* sb = (const float*)d_in[4];  // (784,)
    float* out = (float*)d_out;               // (4,256,56,56)

    const int smem_bytes = SMEM_FLOATS * (int)sizeof(float);  // 110656
    cudaFuncSetAttribute(inv_fused_kernel,
                         cudaFuncAttributeMaxDynamicSharedMemorySize, smem_bytes);

    dim3 grid(WW / TW, HH, BB);   // (2, 56, 4) = 448 blocks
    inv_fused_kernel<<<grid, NTHREADS, smem_bytes>>>(x, rw, rb, sw, sb, out);
}